// round 16
// baseline (speedup 1.0000x reference)
#include <cuda_runtime.h>
#include <cuda_fp16.h>
#include <cstdint>

#define IN_F  4096
#define OUT_F 4096
#define MTOT  2048

// fp16 scratch + barrier state (device globals: no allocation in kernel_launch)
__device__ __half g_wh[(size_t)OUT_F * IN_F];   // w_q * s_w, [o, k] K-major
__device__ __half g_xh[(size_t)MTOT  * IN_F];   // permuted x, [m, k] K-major
__device__ unsigned g_cnt = 0;                  // barrier arrivals (self-resetting)
__device__ unsigned g_rel = 0;                  // barrier release epoch (monotonic)

// Tile 128(M) x 128(N), BK = 64. 16 m-tiles x 32 n-tiles = 512 tiles x 64 k-iters.
static constexpr uint32_t TOTAL_CHUNKS = 32768u;
static constexpr uint32_t N_WITEMS     = 1048576u;    // 4096 rows x 256 16B-segments
static constexpr uint32_t A_BYTES      = 16384;
static constexpr uint32_t STAGE_BYTES  = 32768;
static constexpr uint32_t GEMM_SMEM    = 3 * STAGE_BYTES;   // 96KB -> 2 CTAs/SM

// ------------------------------------------------------------------ helpers
__device__ __forceinline__ uint32_t smem_u32(const void* p) {
    uint32_t a;
    asm("{ .reg .u64 t; cvta.to.shared.u64 t, %1; cvt.u32.u64 %0, t; }" : "=r"(a) : "l"(p));
    return a;
}
__device__ __forceinline__ uint32_t sw128(uint32_t off) { return off ^ ((off >> 3) & 0x70); }
__device__ __forceinline__ void cpa16(uint32_t dst, const void* src) {
    asm volatile("cp.async.cg.shared.global [%0], [%1], 16;" :: "r"(dst), "l"(src));
}
__device__ __forceinline__ void redadd(float* p, float v) {
    asm volatile("red.global.add.f32 [%0], %1;" :: "l"(p), "f"(v) : "memory");
}
#define LDSM4(r0, r1, r2, r3, addr) \
    asm volatile("ldmatrix.sync.aligned.m8n8.x4.shared.b16 {%0,%1,%2,%3}, [%4];" \
        : "=r"(r0), "=r"(r1), "=r"(r2), "=r"(r3) : "r"(addr))
#define MMA16816(d0, d1, d2, d3, a0, a1, a2, a3, b0, b1) \
    asm volatile("mma.sync.aligned.m16n8k16.row.col.f32.f16.f16.f32 " \
        "{%0,%1,%2,%3},{%4,%5,%6,%7},{%8,%9},{%0,%1,%2,%3};" \
        : "+f"(d0), "+f"(d1), "+f"(d2), "+f"(d3) \
        : "r"(a0), "r"(a1), "r"(a2), "r"(a3), "r"(b0), "r"(b1))

// w item u (64B of wq): o = u>>8, seg = u&255 -> cols [seg*16, seg*16+16)
__device__ __forceinline__ void w_item(const int* __restrict__ wq,
                                       const float* __restrict__ sw,
                                       uint32_t u, int4 w[4], float& s) {
    const uint32_t o = u >> 8, seg = u & 255u;
    const int4* p = reinterpret_cast<const int4*>(wq + (size_t)o * IN_F + seg * 16u);
    w[0] = __ldcs(p);     w[1] = __ldcs(p + 1);
    w[2] = __ldcs(p + 2); w[3] = __ldcs(p + 3);
    s = __ldg(sw + (seg >> 3) * OUT_F + o);
}
__device__ __forceinline__ void w_emit(uint32_t u, const int4 w[4], float s) {
    uint4 v0, v1;
    {
        __half2 h0 = __floats2half2_rn(w[0].x * s, w[0].y * s);
        __half2 h1 = __floats2half2_rn(w[0].z * s, w[0].w * s);
        __half2 h2 = __floats2half2_rn(w[1].x * s, w[1].y * s);
        __half2 h3 = __floats2half2_rn(w[1].z * s, w[1].w * s);
        v0.x = *reinterpret_cast<const uint32_t*>(&h0);
        v0.y = *reinterpret_cast<const uint32_t*>(&h1);
        v0.z = *reinterpret_cast<const uint32_t*>(&h2);
        v0.w = *reinterpret_cast<const uint32_t*>(&h3);
    }
    {
        __half2 h0 = __floats2half2_rn(w[2].x * s, w[2].y * s);
        __half2 h1 = __floats2half2_rn(w[2].z * s, w[2].w * s);
        __half2 h2 = __floats2half2_rn(w[3].x * s, w[3].y * s);
        __half2 h3 = __floats2half2_rn(w[3].z * s, w[3].w * s);
        v1.x = *reinterpret_cast<const uint32_t*>(&h0);
        v1.y = *reinterpret_cast<const uint32_t*>(&h1);
        v1.z = *reinterpret_cast<const uint32_t*>(&h2);
        v1.w = *reinterpret_cast<const uint32_t*>(&h3);
    }
    const uint32_t o = u >> 8, seg = u & 255u;
    uint4* dst = reinterpret_cast<uint4*>(g_wh + (size_t)o * IN_F + seg * 16u);
    __stcs(dst, v0);
    __stcs(dst + 1, v1);
}

// ---------------------------------------------------------- GEMM pieces (R13, unchanged)
__device__ __forceinline__ void load_chunk(uint32_t sb, uint32_t chunk, int tid) {
    const uint32_t t = chunk >> 6;
    const int m0 = (int)(t >> 5) * 128;
    const int n0 = (int)(t & 31u) * 128;
    const int k0 = (int)(chunk & 63u) * 64;
#pragma unroll
    for (int c = 0; c < 8; ++c) {                 // A: 128 rows x 8 chunks of 16B
        int idx = tid + c * 128;
        int row = idx >> 3, ch = idx & 7;
        cpa16(sb + sw128((uint32_t)row * 128u + (uint32_t)ch * 16u),
              g_xh + (size_t)(m0 + row) * IN_F + k0 + ch * 8);
    }
#pragma unroll
    for (int c = 0; c < 8; ++c) {                 // B: 128 rows x 8 chunks
        int idx = tid + c * 128;
        int row = idx >> 3, ch = idx & 7;
        cpa16(sb + A_BYTES + sw128((uint32_t)row * 128u + (uint32_t)ch * 16u),
              g_wh + (size_t)(n0 + row) * IN_F + k0 + ch * 8);
    }
}

__device__ __forceinline__ void frag_load(uint32_t sA, uint32_t sB, int s,
                                          int arow_l, int a_c, int brow_l, int b_c,
                                          int wm, int wn, uint32_t a[4][4], uint32_t b[4][4]) {
#pragma unroll
    for (int mi = 0; mi < 4; ++mi) {
        uint32_t off = (uint32_t)((wm * 64 + mi * 16 + arow_l) * 128 + (s * 2 + a_c) * 16);
        LDSM4(a[mi][0], a[mi][1], a[mi][2], a[mi][3], sA + sw128(off));
    }
#pragma unroll
    for (int nb = 0; nb < 4; ++nb) {
        uint32_t off = (uint32_t)((wn * 64 + nb * 16 + brow_l) * 128 + (s * 2 + b_c) * 16);
        LDSM4(b[nb][0], b[nb][1], b[nb][2], b[nb][3], sB + sw128(off));
    }
}

__device__ __forceinline__ void frag_mma(const uint32_t a[4][4], const uint32_t b[4][4],
                                         float acc[4][8][4]) {
#pragma unroll
    for (int mi = 0; mi < 4; ++mi)
#pragma unroll
        for (int ni = 0; ni < 8; ++ni) {
            uint32_t b0 = b[ni >> 1][(ni & 1) * 2];
            uint32_t b1 = b[ni >> 1][(ni & 1) * 2 + 1];
            MMA16816(acc[mi][ni][0], acc[mi][ni][1], acc[mi][ni][2], acc[mi][ni][3],
                     a[mi][0], a[mi][1], a[mi][2], a[mi][3], b0, b1);
        }
}

// ---------------------------------------------------------- fused persistent kernel
__global__ void __launch_bounds__(128, 2) fused_kernel(const int* __restrict__ wq,
                                                       const float* __restrict__ sw,
                                                       const float* __restrict__ x,
                                                       const int* __restrict__ perm32,
                                                       const float* __restrict__ bias,
                                                       float* __restrict__ out,
                                                       int ncta_) {
    extern __shared__ char smem[];
    const uint32_t sbase = smem_u32(smem);
    const uint32_t ncta = (uint32_t)ncta_;
    const int tid  = threadIdx.x;
    const uint32_t cta = blockIdx.x;
    __shared__ int is64s;

    // ========================== Phase A ==========================
    if (tid == 0) {
        // jnp int64 vs int32 detection: int64 LE => odd 32-bit words all zero.
        int acc = 0;
#pragma unroll
        for (int t = 1; t < 32; t += 2) acc |= perm32[t];
        is64s = (acc == 0) ? 1 : 0;
    }
    __syncthreads();
    const int sh = is64s;

    // (a) x permute + fp32->fp16: rows strided over CTAs, cp.async double-buffered.
    //     row buffer = 16KB fp32; two buffers in stage slot 0 (sbase + {0,16KB}).
    {
        float* rb[2] = { reinterpret_cast<float*>(smem),
                         reinterpret_cast<float*>(smem + 16384) };
        uint32_t m = cta, i = 0;
        if (m < MTOT) {
#pragma unroll
            for (int c = 0; c < 8; ++c)                    // prologue: row m -> buf0
                cpa16(sbase + (uint32_t)(tid * 16 + c * 2048),
                      x + (size_t)m * IN_F + tid * 4 + c * 512);
            asm volatile("cp.async.commit_group;" ::: "memory");
        }
        for (; m < MTOT; m += ncta, ++i) {
            const uint32_t mn = m + ncta;
            if (mn < MTOT) {
                const uint32_t sb = sbase + ((i + 1u) & 1u) * 16384u;
#pragma unroll
                for (int c = 0; c < 8; ++c)
                    cpa16(sb + (uint32_t)(tid * 16 + c * 2048),
                          x + (size_t)mn * IN_F + tid * 4 + c * 512);
            }
            asm volatile("cp.async.commit_group;" ::: "memory");
            asm volatile("cp.async.wait_group 1;" ::: "memory");
            __syncthreads();
            const float* rowbuf = rb[i & 1u];
            const int j0 = tid * 32;
            __half* dst = g_xh + (size_t)m * IN_F + j0;
#pragma unroll
            for (int h = 0; h < 4; ++h) {
                int jb = j0 + h * 8;
                float v[8];
#pragma unroll
                for (int q = 0; q < 8; ++q) v[q] = rowbuf[perm32[(jb + q) << sh]];
                __half2 p0 = __floats2half2_rn(v[0], v[1]);
                __half2 p1 = __floats2half2_rn(v[2], v[3]);
                __half2 p2 = __floats2half2_rn(v[4], v[5]);
                __half2 p3 = __floats2half2_rn(v[6], v[7]);
                uint4 u;
                u.x = *reinterpret_cast<uint32_t*>(&p0);
                u.y = *reinterpret_cast<uint32_t*>(&p1);
                u.z = *reinterpret_cast<uint32_t*>(&p2);
                u.w = *reinterpret_cast<uint32_t*>(&p3);
                __stcs(reinterpret_cast<uint4*>(dst + h * 8), u);
            }
            __syncthreads();                               // buffer reusable
        }
        asm volatile("cp.async.wait_group 0;" ::: "memory");
    }

    // (b) w_q * s_w -> fp16, unrolled x4 (16 independent int4 LDGs in flight)
    {
        const uint32_t u0 = (cta * N_WITEMS) / ncta;
        const uint32_t u1 = ((cta + 1u) * N_WITEMS) / ncta;
        uint32_t u = u0 + (uint32_t)tid;
        for (; u + 384u < u1; u += 512u) {
            int4 w0[4], w1[4], w2[4], w3[4];
            float s0, s1, s2, s3;
            w_item(wq, sw, u,        w0, s0);
            w_item(wq, sw, u + 128u, w1, s1);
            w_item(wq, sw, u + 256u, w2, s2);
            w_item(wq, sw, u + 384u, w3, s3);
            w_emit(u,        w0, s0);
            w_emit(u + 128u, w1, s1);
            w_emit(u + 256u, w2, s2);
            w_emit(u + 384u, w3, s3);
        }
        for (; u < u1; u += 128u) {
            int4 w0[4]; float s0;
            w_item(wq, sw, u, w0, s0);
            w_emit(u, w0, s0);
        }
    }

    // (c) split-tile bias prefill
    __syncthreads();
    if (cta >= 1u) {
        const uint32_t s = (cta * TOTAL_CHUNKS) / ncta;
        if (s & 63u) {
            float* rowbuf = reinterpret_cast<float*>(smem);
            const uint32_t t = s >> 6;
            const int m0 = (int)(t >> 5) * 128, n0 = (int)(t & 31u) * 128;
            rowbuf[tid] = bias[n0 + tid];
            __syncthreads();
#pragma unroll 4
            for (int it = 0; it < 32; ++it) {             // 128 rows x 32 float4
                int idx = tid + it * 128;
                int r = idx >> 5, c4 = idx & 31;
                float4 v = make_float4(rowbuf[c4 * 4], rowbuf[c4 * 4 + 1],
                                       rowbuf[c4 * 4 + 2], rowbuf[c4 * 4 + 3]);
                __stcs(reinterpret_cast<float4*>(out + (size_t)(m0 + r) * OUT_F + n0) + c4, v);
            }
        }
    }

    // ===================== grid barrier (replay-safe) =====================
    __threadfence();
    __syncthreads();
    if (tid == 0) {
        unsigned rel0 = atomicAdd(&g_rel, 0u);
        unsigned old  = atomicAdd(&g_cnt, 1u);
        if (old == ncta - 1u) { g_cnt = 0u; __threadfence(); atomicAdd(&g_rel, 1u); }
        else { while (atomicAdd(&g_rel, 0u) == rel0) __nanosleep(64); }
        __threadfence();
    }
    __syncthreads();

    // ========================== Phase B: GEMM (R13) ==========================
    const int lane = tid & 31, wid = tid >> 5;
    const int wm = wid & 1, wn = wid >> 1;        // 2 x 2 warp grid, warp tile 64x64
    const int arow_l = (lane & 7) + ((lane >> 3) & 1) * 8;
    const int a_c    = lane >> 4;
    const int brow_l = (lane & 7) + ((lane >> 4) & 1) * 8;
    const int b_c    = (lane >> 3) & 1;

    const uint32_t start = (cta * TOTAL_CHUNKS) / ncta;
    const uint32_t end   = ((cta + 1u) * TOTAL_CHUNKS) / ncta;

    float acc[4][8][4];
#pragma unroll
    for (int i = 0; i < 4; ++i)
#pragma unroll
        for (int j = 0; j < 8; ++j)
#pragma unroll
            for (int q = 0; q < 4; ++q) acc[i][j][q] = 0.f;

    uint32_t afrag[2][4][4], bfrag[2][4][4];
    uint32_t seg_first = start & 63u;

    load_chunk(sbase + (start % 3u) * STAGE_BYTES, start, tid);
    asm volatile("cp.async.commit_group;" ::: "memory");
    if (start + 1u < end)
        load_chunk(sbase + ((start + 1u) % 3u) * STAGE_BYTES, start + 1u, tid);
    asm volatile("cp.async.commit_group;" ::: "memory");

    for (uint32_t ch = start; ch < end; ++ch) {
        asm volatile("cp.async.wait_group 1;" ::: "memory");
        __syncthreads();

        const uint32_t sA = sbase + (ch % 3u) * STAGE_BYTES;
        const uint32_t sB = sA + A_BYTES;

        frag_load(sA, sB, 0, arow_l, a_c, brow_l, b_c, wm, wn, afrag[0], bfrag[0]);

        if (ch + 2u < end)
            load_chunk(sbase + ((ch + 2u) % 3u) * STAGE_BYTES, ch + 2u, tid);
        asm volatile("cp.async.commit_group;" ::: "memory");

#pragma unroll
        for (int s = 0; s < 4; ++s) {
            if (s < 3)
                frag_load(sA, sB, s + 1, arow_l, a_c, brow_l, b_c, wm, wn,
                          afrag[(s + 1) & 1], bfrag[(s + 1) & 1]);
            frag_mma(afrag[s & 1], bfrag[s & 1], acc);
        }

        const uint32_t kidx = ch & 63u;
        const bool tile_done = (kidx == 63u) || (ch + 1u == end);
        if (tile_done) {
            const uint32_t t = ch >> 6;
            const int n0 = (int)(t & 31u) * 128;
            const int m0 = (int)(t >> 5) * 128;
            const int ncol = n0 + wn * 64 + (lane & 3) * 2;
            const int mrow = m0 + wm * 64 + (lane >> 2);
            const bool full = (seg_first == 0u && kidx == 63u);
            if (full) {                           // sole writer: direct store with bias
#pragma unroll
                for (int mi = 0; mi < 4; ++mi) {
                    float* r0 = out + (size_t)(mrow + mi * 16) * OUT_F;
                    float* r1 = r0 + 8 * OUT_F;
#pragma unroll
                    for (int ni = 0; ni < 8; ++ni) {
                        float2 bv = *reinterpret_cast<const float2*>(bias + ncol + ni * 8);
                        float2 v0, v1;
                        v0.x = acc[mi][ni][0] + bv.x;
                        v0.y = acc[mi][ni][1] + bv.y;
                        v1.x = acc[mi][ni][2] + bv.x;
                        v1.y = acc[mi][ni][3] + bv.y;
                        __stcs(reinterpret_cast<float2*>(r0 + ncol + ni * 8), v0);
                        __stcs(reinterpret_cast<float2*>(r1 + ncol + ni * 8), v1);
                    }
                }
            } else {                              // split tile: accumulate into prefilled out
#pragma unroll
                for (int mi = 0; mi < 4; ++mi) {
                    float* r0 = out + (size_t)(mrow + mi * 16) * OUT_F;
                    float* r1 = r0 + 8 * OUT_F;
#pragma unroll
                    for (int ni = 0; ni < 8; ++ni) {
                        redadd(r0 + ncol + ni * 8,     acc[mi][ni][0]);
                        redadd(r0 + ncol + ni * 8 + 1, acc[mi][ni][1]);
                        redadd(r1 + ncol + ni * 8,     acc[mi][ni][2]);
                        redadd(r1 + ncol + ni * 8 + 1, acc[mi][ni][3]);
                    }
                }
            }
#pragma unroll
            for (int i2 = 0; i2 < 4; ++i2)
#pragma unroll
                for (int j = 0; j < 8; ++j)
#pragma unroll
                    for (int q = 0; q < 4; ++q) acc[i2][j][q] = 0.f;
            seg_first = 0u;
        }
    }
}

// ---------------------------------------------------------- launch
extern "C" void kernel_launch(void* const* d_in, const int* in_sizes, int n_in,
                              void* d_out, int out_size) {
    const float* x    = (const float*)d_in[0];
    const int*   wq   = (const int*)d_in[1];
    const float* sw   = (const float*)d_in[2];
    const int*   perm = (const int*)d_in[3];   // int32 or int64 — detected on device
    const float* bias = (const float*)d_in[4];
    float* out = (float*)d_out;

    int nsm = 148;
    cudaDeviceGetAttribute(&nsm, cudaDevAttrMultiProcessorCount, 0);
    const int ncta = 2 * nsm;                  // 2 CTAs per SM, all resident (barrier-safe)

    cudaFuncSetAttribute(fused_kernel, cudaFuncAttributeMaxDynamicSharedMemorySize, GEMM_SMEM);
    fused_kernel<<<ncta, 128, GEMM_SMEM>>>(wq, sw, x, perm, bias, out, ncta);
}

// round 17
// speedup vs baseline: 1.1995x; 1.1995x over previous
#include <cuda_runtime.h>
#include <cuda_fp16.h>
#include <cstdint>

#define IN_F  4096
#define OUT_F 4096
#define MTOT  2048

// fp16 scratch (device globals: no allocation in kernel_launch)
__device__ __half g_wh[(size_t)OUT_F * IN_F];   // w_q * s_w, [o, k] K-major
__device__ __half g_xh[(size_t)MTOT  * IN_F];   // permuted x, [m, k] K-major

// Tile 128(M) x 128(N), BK = 64. 16 m-tiles x 32 n-tiles = 512 tiles x 64 k-iters.
static constexpr uint32_t TOTAL_CHUNKS = 32768u;
static constexpr uint32_t A_BYTES      = 16384;       // A 16KB + B 16KB per stage
static constexpr uint32_t STAGE_BYTES  = 32768;
static constexpr uint32_t GEMM_SMEM    = 3 * STAGE_BYTES;   // 96KB -> 2 CTAs/SM

// ------------------------------------------------------------------ helpers
__device__ __forceinline__ uint32_t smem_u32(const void* p) {
    uint32_t a;
    asm("{ .reg .u64 t; cvta.to.shared.u64 t, %1; cvt.u32.u64 %0, t; }" : "=r"(a) : "l"(p));
    return a;
}
__device__ __forceinline__ uint32_t sw128(uint32_t off) { return off ^ ((off >> 3) & 0x70); }
__device__ __forceinline__ void cpa16(uint32_t dst, const void* src) {
    asm volatile("cp.async.cg.shared.global [%0], [%1], 16;" :: "r"(dst), "l"(src));
}
__device__ __forceinline__ void redadd(float* p, float v) {
    asm volatile("red.global.add.f32 [%0], %1;" :: "l"(p), "f"(v) : "memory");
}
#define LDSM4(r0, r1, r2, r3, addr) \
    asm volatile("ldmatrix.sync.aligned.m8n8.x4.shared.b16 {%0,%1,%2,%3}, [%4];" \
        : "=r"(r0), "=r"(r1), "=r"(r2), "=r"(r3) : "r"(addr))
#define MMA16816(d0, d1, d2, d3, a0, a1, a2, a3, b0, b1) \
    asm volatile("mma.sync.aligned.m16n8k16.row.col.f32.f16.f16.f32 " \
        "{%0,%1,%2,%3},{%4,%5,%6,%7},{%8,%9},{%0,%1,%2,%3};" \
        : "+f"(d0), "+f"(d1), "+f"(d2), "+f"(d3) \
        : "r"(a0), "r"(a1), "r"(a2), "r"(a3), "r"(b0), "r"(b1))

// ---------------------------------------------------------- fused prep (no prefill branch)
// blocks [0, 4096):       w-row o; w_q * s_w -> fp16
// blocks [4096, 6144):    x-row m; permute + fp32->fp16
__global__ void __launch_bounds__(256) prep_kernel(const int* __restrict__ wq,
                                                   const float* __restrict__ sw,
                                                   const float* __restrict__ x,
                                                   const int* __restrict__ perm32) {
    __shared__ float row[IN_F];
    __shared__ int is64s;
    const int tid = threadIdx.x;

    if (blockIdx.x < 4096) {
        const int o = blockIdx.x;
        const float s = __ldg(sw + (tid >> 3) * OUT_F + o);   // 8-thread broadcast
        const int k0 = tid * 16;
        const int4* p = reinterpret_cast<const int4*>(wq + (size_t)o * IN_F + k0);
        int4 w0 = __ldcs(p), w1 = __ldcs(p + 1), w2 = __ldcs(p + 2), w3 = __ldcs(p + 3);
        uint4 v0, v1;
        {
            __half2 h0 = __floats2half2_rn(w0.x * s, w0.y * s);
            __half2 h1 = __floats2half2_rn(w0.z * s, w0.w * s);
            __half2 h2 = __floats2half2_rn(w1.x * s, w1.y * s);
            __half2 h3 = __floats2half2_rn(w1.z * s, w1.w * s);
            v0.x = *reinterpret_cast<uint32_t*>(&h0);
            v0.y = *reinterpret_cast<uint32_t*>(&h1);
            v0.z = *reinterpret_cast<uint32_t*>(&h2);
            v0.w = *reinterpret_cast<uint32_t*>(&h3);
        }
        {
            __half2 h0 = __floats2half2_rn(w2.x * s, w2.y * s);
            __half2 h1 = __floats2half2_rn(w2.z * s, w2.w * s);
            __half2 h2 = __floats2half2_rn(w3.x * s, w3.y * s);
            __half2 h3 = __floats2half2_rn(w3.z * s, w3.w * s);
            v1.x = *reinterpret_cast<uint32_t*>(&h0);
            v1.y = *reinterpret_cast<uint32_t*>(&h1);
            v1.z = *reinterpret_cast<uint32_t*>(&h2);
            v1.w = *reinterpret_cast<uint32_t*>(&h3);
        }
        uint4* dst = reinterpret_cast<uint4*>(g_wh + (size_t)o * IN_F + k0);
        __stcs(dst, v0);
        __stcs(dst + 1, v1);
        return;
    }

    const int m = blockIdx.x - 4096;
    const float4* src = reinterpret_cast<const float4*>(x + (size_t)m * IN_F);
#pragma unroll
    for (int i = 0; i < 4; ++i)
        reinterpret_cast<float4*>(row)[tid + i * 256] = __ldcs(src + tid + i * 256);
    if (tid == 0) {
        // jnp int64 vs int32 detection: int64 LE => odd 32-bit words all zero.
        int acc = 0;
#pragma unroll
        for (int t = 1; t < 32; t += 2) acc |= perm32[t];
        is64s = (acc == 0) ? 1 : 0;
    }
    __syncthreads();
    const int sh = is64s;
    const int j0 = tid * 16;
    __half* dst = g_xh + (size_t)m * IN_F + j0;
#pragma unroll
    for (int h = 0; h < 2; ++h) {
        int jb = j0 + h * 8;
        float v[8];
#pragma unroll
        for (int i = 0; i < 8; ++i) v[i] = row[perm32[(jb + i) << sh]];
        __half2 p0 = __floats2half2_rn(v[0], v[1]);
        __half2 p1 = __floats2half2_rn(v[2], v[3]);
        __half2 p2 = __floats2half2_rn(v[4], v[5]);
        __half2 p3 = __floats2half2_rn(v[6], v[7]);
        uint4 u;
        u.x = *reinterpret_cast<uint32_t*>(&p0);
        u.y = *reinterpret_cast<uint32_t*>(&p1);
        u.z = *reinterpret_cast<uint32_t*>(&p2);
        u.w = *reinterpret_cast<uint32_t*>(&p3);
        __stcs(reinterpret_cast<uint4*>(dst + h * 8), u);
    }
}

// ---------------------------------------------------------- GEMM: persistent, 2 CTAs/SM
__device__ __forceinline__ void load_chunk(uint32_t sb, uint32_t chunk, int tid) {
    const uint32_t t = chunk >> 6;
    const int m0 = (int)(t >> 5) * 128;
    const int n0 = (int)(t & 31u) * 128;
    const int k0 = (int)(chunk & 63u) * 64;
#pragma unroll
    for (int c = 0; c < 8; ++c) {                 // A: 128 rows x 8 chunks of 16B
        int idx = tid + c * 128;
        int row = idx >> 3, ch = idx & 7;
        cpa16(sb + sw128((uint32_t)row * 128u + (uint32_t)ch * 16u),
              g_xh + (size_t)(m0 + row) * IN_F + k0 + ch * 8);
    }
#pragma unroll
    for (int c = 0; c < 8; ++c) {                 // B: 128 rows x 8 chunks
        int idx = tid + c * 128;
        int row = idx >> 3, ch = idx & 7;
        cpa16(sb + A_BYTES + sw128((uint32_t)row * 128u + (uint32_t)ch * 16u),
              g_wh + (size_t)(n0 + row) * IN_F + k0 + ch * 8);
    }
}

__device__ __forceinline__ void frag_load(uint32_t sA, uint32_t sB, int s,
                                          int arow_l, int a_c, int brow_l, int b_c,
                                          int wm, int wn, uint32_t a[4][4], uint32_t b[4][4]) {
#pragma unroll
    for (int mi = 0; mi < 4; ++mi) {
        uint32_t off = (uint32_t)((wm * 64 + mi * 16 + arow_l) * 128 + (s * 2 + a_c) * 16);
        LDSM4(a[mi][0], a[mi][1], a[mi][2], a[mi][3], sA + sw128(off));
    }
#pragma unroll
    for (int nb = 0; nb < 4; ++nb) {
        uint32_t off = (uint32_t)((wn * 64 + nb * 16 + brow_l) * 128 + (s * 2 + b_c) * 16);
        LDSM4(b[nb][0], b[nb][1], b[nb][2], b[nb][3], sB + sw128(off));
    }
}

__device__ __forceinline__ void frag_mma(const uint32_t a[4][4], const uint32_t b[4][4],
                                         float acc[4][8][4]) {
#pragma unroll
    for (int mi = 0; mi < 4; ++mi)
#pragma unroll
        for (int ni = 0; ni < 8; ++ni) {
            uint32_t b0 = b[ni >> 1][(ni & 1) * 2];
            uint32_t b1 = b[ni >> 1][(ni & 1) * 2 + 1];
            MMA16816(acc[mi][ni][0], acc[mi][ni][1], acc[mi][ni][2], acc[mi][ni][3],
                     a[mi][0], a[mi][1], a[mi][2], a[mi][3], b0, b1);
        }
}

__global__ void __launch_bounds__(128, 2) gemm_kernel(const float* __restrict__ bias,
                                                      float* __restrict__ out,
                                                      int ncta_) {
    extern __shared__ char smem[];
    const uint32_t sbase = smem_u32(smem);
    const uint32_t ncta = (uint32_t)ncta_;
    const int tid  = threadIdx.x;
    const int lane = tid & 31, wid = tid >> 5;
    const int wm = wid & 1, wn = wid >> 1;        // 2 x 2 warp grid
    const int arow_l = (lane & 7) + ((lane >> 3) & 1) * 8;
    const int a_c    = lane >> 4;
    const int brow_l = (lane & 7) + ((lane >> 4) & 1) * 8;
    const int b_c    = (lane >> 3) & 1;

    const uint32_t cta = blockIdx.x;
    const uint32_t start = (cta * TOTAL_CHUNKS) / ncta;
    const uint32_t end   = ((cta + 1u) * TOTAL_CHUNKS) / ncta;

    // ---- split-tile bias prefill: depends only on bias/out, NOT on prep outputs.
    // Runs BEFORE the PDL gate, so it overlaps the prep kernel. Writers of this tile
    // (this CTA's reds and CTA-1's reds) both occur >=tens of microseconds later.
    if (cta >= 1u && (start & 63u)) {
        float* rowbuf = reinterpret_cast<float*>(smem);
        const uint32_t t = start >> 6;
        const int m0 = (int)(t >> 5) * 128, n0 = (int)(t & 31u) * 128;
        rowbuf[tid] = bias[n0 + tid];
        __syncthreads();
#pragma unroll 4
        for (int it = 0; it < 32; ++it) {                 // 128 rows x 32 float4
            int idx = tid + it * 128;
            int r = idx >> 5, c4 = idx & 31;
            float4 v = make_float4(rowbuf[c4 * 4], rowbuf[c4 * 4 + 1],
                                   rowbuf[c4 * 4 + 2], rowbuf[c4 * 4 + 3]);
            __stcs(reinterpret_cast<float4*>(out + (size_t)(m0 + r) * OUT_F + n0) + c4, v);
        }
        __syncthreads();
    }

#if __CUDA_ARCH__ >= 900
    cudaGridDependencySynchronize();              // PDL: wait for prep outputs
#endif

    float acc[4][8][4];
#pragma unroll
    for (int i = 0; i < 4; ++i)
#pragma unroll
        for (int j = 0; j < 8; ++j)
#pragma unroll
            for (int q = 0; q < 4; ++q) acc[i][j][q] = 0.f;

    uint32_t afrag[2][4][4], bfrag[2][4][4];
    uint32_t seg_first = start & 63u;

    // prologue: chunks start, start+1 (slot = chunk % 3)
    load_chunk(sbase + (start % 3u) * STAGE_BYTES, start, tid);
    asm volatile("cp.async.commit_group;" ::: "memory");
    if (start + 1u < end)
        load_chunk(sbase + ((start + 1u) % 3u) * STAGE_BYTES, start + 1u, tid);
    asm volatile("cp.async.commit_group;" ::: "memory");

    for (uint32_t ch = start; ch < end; ++ch) {
        asm volatile("cp.async.wait_group 1;" ::: "memory");
        __syncthreads();

        const uint32_t sA = sbase + (ch % 3u) * STAGE_BYTES;
        const uint32_t sB = sA + A_BYTES;

        // Step-0 fragments FIRST, so they aren't queued behind the LDGSTS burst.
        frag_load(sA, sB, 0, arow_l, a_c, brow_l, b_c, wm, wn, afrag[0], bfrag[0]);

        if (ch + 2u < end)
            load_chunk(sbase + ((ch + 2u) % 3u) * STAGE_BYTES, ch + 2u, tid);
        asm volatile("cp.async.commit_group;" ::: "memory");

#pragma unroll
        for (int s = 0; s < 4; ++s) {
            if (s < 3)
                frag_load(sA, sB, s + 1, arow_l, a_c, brow_l, b_c, wm, wn,
                          afrag[(s + 1) & 1], bfrag[(s + 1) & 1]);
            frag_mma(afrag[s & 1], bfrag[s & 1], acc);
        }

        const uint32_t kidx = ch & 63u;
        const bool tile_done = (kidx == 63u) || (ch + 1u == end);
        if (tile_done) {
            const uint32_t t = ch >> 6;
            const int n0 = (int)(t & 31u) * 128;
            const int m0 = (int)(t >> 5) * 128;
            const int ncol = n0 + wn * 64 + (lane & 3) * 2;
            const int mrow = m0 + wm * 64 + (lane >> 2);
            const bool full = (seg_first == 0u && kidx == 63u);
            if (full) {                           // sole writer: direct store with bias
#pragma unroll
                for (int mi = 0; mi < 4; ++mi) {
                    float* r0 = out + (size_t)(mrow + mi * 16) * OUT_F;
                    float* r1 = r0 + 8 * OUT_F;
#pragma unroll
                    for (int ni = 0; ni < 8; ++ni) {
                        float2 bv = *reinterpret_cast<const float2*>(bias + ncol + ni * 8);
                        float2 v0, v1;
                        v0.x = acc[mi][ni][0] + bv.x;
                        v0.y = acc[mi][ni][1] + bv.y;
                        v1.x = acc[mi][ni][2] + bv.x;
                        v1.y = acc[mi][ni][3] + bv.y;
                        __stcs(reinterpret_cast<float2*>(r0 + ncol + ni * 8), v0);
                        __stcs(reinterpret_cast<float2*>(r1 + ncol + ni * 8), v1);
                    }
                }
            } else {                              // split tile: accumulate into prefilled out
#pragma unroll
                for (int mi = 0; mi < 4; ++mi) {
                    float* r0 = out + (size_t)(mrow + mi * 16) * OUT_F;
                    float* r1 = r0 + 8 * OUT_F;
#pragma unroll
                    for (int ni = 0; ni < 8; ++ni) {
                        redadd(r0 + ncol + ni * 8,     acc[mi][ni][0]);
                        redadd(r0 + ncol + ni * 8 + 1, acc[mi][ni][1]);
                        redadd(r1 + ncol + ni * 8,     acc[mi][ni][2]);
                        redadd(r1 + ncol + ni * 8 + 1, acc[mi][ni][3]);
                    }
                }
            }
#pragma unroll
            for (int i2 = 0; i2 < 4; ++i2)
#pragma unroll
                for (int j = 0; j < 8; ++j)
#pragma unroll
                    for (int q = 0; q < 4; ++q) acc[i2][j][q] = 0.f;
            seg_first = 0u;
        }
    }
}

// ---------------------------------------------------------- launch
extern "C" void kernel_launch(void* const* d_in, const int* in_sizes, int n_in,
                              void* d_out, int out_size) {
    const float* x    = (const float*)d_in[0];
    const int*   wq   = (const int*)d_in[1];
    const float* sw   = (const float*)d_in[2];
    const int*   perm = (const int*)d_in[3];   // int32 or int64 — detected on device
    const float* bias = (const float*)d_in[4];
    float* out = (float*)d_out;

    int nsm = 148;
    cudaDeviceGetAttribute(&nsm, cudaDevAttrMultiProcessorCount, 0);
    const int ncta = 2 * nsm;                  // 2 CTAs per SM

    prep_kernel<<<4096 + MTOT, 256>>>(wq, sw, x, perm);

    cudaFuncSetAttribute(gemm_kernel, cudaFuncAttributeMaxDynamicSharedMemorySize, GEMM_SMEM);

    // PDL launch: GEMM CTAs start while prep runs; the bias prefill executes before
    // the dependency gate (it doesn't read prep outputs), then the mainloop gates.
    cudaLaunchConfig_t cfg = {};
    cfg.gridDim  = dim3((unsigned)ncta, 1, 1);
    cfg.blockDim = dim3(128, 1, 1);
    cfg.dynamicSmemBytes = GEMM_SMEM;
    cudaLaunchAttribute attrs[1];
    attrs[0].id = cudaLaunchAttributeProgrammaticStreamSerialization;
    attrs[0].val.programmaticStreamSerializationAllowed = 1;
    cfg.attrs = attrs;
    cfg.numAttrs = 1;
    cudaError_t err = cudaLaunchKernelEx(&cfg, gemm_kernel, bias, out, ncta);
    if (err != cudaSuccess) {                  // fallback: plain serialized launch
        gemm_kernel<<<ncta, 128, GEMM_SMEM>>>(bias, out, ncta);
    }
}